// round 15
// baseline (speedup 1.0000x reference)
#include <cuda_runtime.h>
#include <cuda_fp16.h>
#include <cstdint>
#include <cstddef>

// Problem constants
#define NROWS 4096
#define INF   4096
#define OUTF  4096

// GEMM tiling (fp16 HMMA)
#define BM 128
#define BN 256
#define BKE 64                    // fp16 elements per k-tile
#define STAGES 4
#define KT (INF / BKE)            // 64
#define LDSE 72                   // padded smem row stride in fp16 (144 B)
#define ROWB (LDSE * 2)           // 144 bytes per row
#define XTILE_B (BM * ROWB)       // 18432
#define WTILE_B (BN * ROWB)       // 36864
#define STAGE_B (XTILE_B + WTILE_B)      // 55296
#define SMEM_TOTAL (STAGES * STAGE_B)    // 221184

#define NTHREADS 512

// Persistent scratch
__device__ __half g_x[(size_t)NROWS * INF];   // fp16(x)
__device__ __half g_w[(size_t)OUTF  * INF];   // (q - 8) exact

// ---------------------------------------------------------------------------
// Fused prep: blocks [0, XB) convert x; blocks [XB, XB+WB) unpack w
// ---------------------------------------------------------------------------
#define XB ((NROWS * INF / 4) / 256)          // 16384 blocks
#define WB ((OUTF * (INF / 2) / 4) / 256)     // 8192 blocks

__global__ void prep_kernel(const float* __restrict__ x, const int* __restrict__ wp) {
    if (blockIdx.x < XB) {
        int idx = blockIdx.x * blockDim.x + threadIdx.x;
        float4 v = reinterpret_cast<const float4*>(x)[idx];
        __half2 h01 = __floats2half2_rn(v.x, v.y);
        __half2 h23 = __floats2half2_rn(v.z, v.w);
        uint2 pack;
        pack.x = *reinterpret_cast<uint32_t*>(&h01);
        pack.y = *reinterpret_cast<uint32_t*>(&h23);
        reinterpret_cast<uint2*>(g_x)[idx] = pack;
    } else {
        int idx = (blockIdx.x - XB) * blockDim.x + threadIdx.x;
        int4 w = reinterpret_cast<const int4*>(wp)[idx];
        int vals[4] = {w.x, w.y, w.z, w.w};
        __half ob[8];
#pragma unroll
        for (int j = 0; j < 4; ++j) {
            ob[2 * j]     = __int2half_rn((vals[j] & 0xF) - 8);
            ob[2 * j + 1] = __int2half_rn(((vals[j] >> 4) & 0xF) - 8);
        }
        reinterpret_cast<uint4*>(&g_w[(size_t)idx * 8])[0] = *reinterpret_cast<uint4*>(ob);
    }
}

// ---------------------------------------------------------------------------
// GEMM helpers
// ---------------------------------------------------------------------------
#define CP_ASYNC16(dst, src) \
    asm volatile("cp.async.cg.shared.global [%0], [%1], 16;\n" :: "r"(dst), "l"(src))
#define CP_COMMIT() asm volatile("cp.async.commit_group;\n" ::)
#define CP_WAIT(n)  asm volatile("cp.async.wait_group %0;\n" :: "n"(n))

__device__ __forceinline__ void ldmatrix_x4(uint32_t* r, uint32_t addr) {
    asm volatile("ldmatrix.sync.aligned.m8n8.x4.shared.b16 {%0,%1,%2,%3}, [%4];\n"
                 : "=r"(r[0]), "=r"(r[1]), "=r"(r[2]), "=r"(r[3]) : "r"(addr));
}
__device__ __forceinline__ void mma_f16(float* d, const uint32_t* a, const uint32_t* b) {
    asm volatile("mma.sync.aligned.m16n8k16.row.col.f32.f16.f16.f32 "
                 "{%0,%1,%2,%3}, {%4,%5,%6,%7}, {%8,%9}, {%0,%1,%2,%3};\n"
                 : "+f"(d[0]), "+f"(d[1]), "+f"(d[2]), "+f"(d[3])
                 : "r"(a[0]), "r"(a[1]), "r"(a[2]), "r"(a[3]), "r"(b[0]), "r"(b[1]));
}

// Load one stage: X tile (128 x 64 fp16) + W tile (256 x 64 fp16), 512 threads
__device__ __forceinline__ void load_tile(int tid, int bm, int bn, int stage, int kt,
                                          uint32_t sbase) {
    const int kb = kt * BKE;
    uint32_t dstX = sbase + stage * STAGE_B;
    uint32_t dstW = dstX + XTILE_B;
#pragma unroll
    for (int i = 0; i < 2; ++i) {
        int chunk = tid + i * NTHREADS;
        int row = chunk >> 3;
        int c   = chunk & 7;
        CP_ASYNC16(dstX + row * ROWB + c * 16,
                   &g_x[(size_t)(bm + row) * INF + kb + c * 8]);
    }
#pragma unroll
    for (int i = 0; i < 4; ++i) {
        int chunk = tid + i * NTHREADS;
        int row = chunk >> 3;
        int c   = chunk & 7;
        CP_ASYNC16(dstW + row * ROWB + c * 16,
                   &g_w[(size_t)(bn + row) * INF + kb + c * 8]);
    }
}

// ---------------------------------------------------------------------------
// GEMM: out[n,o] = (x . w) * wscale[o] + bias[o]
// 16 warps: wm = warp&1 (64 M rows), wn = warp>>1 (32 N cols). Warp tile 64x32.
// Fragment double-buffering: load frags(ks+1) before issuing mma(ks).
// ---------------------------------------------------------------------------
__global__ void __launch_bounds__(NTHREADS, 1) gemm_f16(
    float* __restrict__ out,
    const float* __restrict__ scales,
    const float* __restrict__ bias)
{
    extern __shared__ char smem[];
    const int tid  = threadIdx.x;
    const int lane = tid & 31;
    const int warp = tid >> 5;
    const int wm   = warp & 1;     // 2 warps along M (64 rows)
    const int wn   = warp >> 1;    // 8 warps along N (32 cols)
    const int bm   = blockIdx.y * BM;
    const int bn   = blockIdx.x * BN;

    uint32_t sb = (uint32_t)__cvta_generic_to_shared(smem);

    // Per-warp ldmatrix base offsets (within a stage), compile-time step per ks
    const uint32_t aOff = (uint32_t)(wm * 64 + (lane & 15)) * ROWB
                        + ((lane >> 4) << 3) * 2;
    const uint32_t bOff = XTILE_B
                        + (uint32_t)(wn * 32 + ((lane >> 4) << 3) + (lane & 7)) * ROWB
                        + (((lane >> 3) & 1) << 3) * 2;

    float acc[4][4][4];
#pragma unroll
    for (int mi = 0; mi < 4; ++mi)
#pragma unroll
        for (int ni = 0; ni < 4; ++ni)
#pragma unroll
            for (int j = 0; j < 4; ++j) acc[mi][ni][j] = 0.0f;

    uint32_t ra[2][4][4];   // double-buffered A fragments
    uint32_t rb[2][4][2];   // double-buffered B fragments

    // Prologue: stages 0..2
#pragma unroll
    for (int s = 0; s < STAGES - 1; ++s) {
        load_tile(tid, bm, bn, s, s, sb);
        CP_COMMIT();
    }

    for (int kt = 0; kt < KT; ++kt) {
        CP_WAIT(STAGES - 2);
        __syncthreads();

        int ld = kt + STAGES - 1;
        if (ld < KT) load_tile(tid, bm, bn, ld & (STAGES - 1), ld, sb);
        CP_COMMIT();

        const uint32_t stBase = sb + (kt & (STAGES - 1)) * STAGE_B;
        const uint32_t aB = stBase + aOff;
        const uint32_t bB = stBase + bOff;

        // Preload frags for ks=0 into buffer 0
#pragma unroll
        for (int nj = 0; nj < 2; ++nj) {
            uint32_t q[4];
            ldmatrix_x4(q, bB + nj * 16 * ROWB);
            rb[0][2 * nj][0] = q[0]; rb[0][2 * nj][1] = q[1];
            rb[0][2 * nj + 1][0] = q[2]; rb[0][2 * nj + 1][1] = q[3];
        }
#pragma unroll
        for (int mi = 0; mi < 4; ++mi)
            ldmatrix_x4(ra[0][mi], aB + mi * 16 * ROWB);

#pragma unroll
        for (int ks = 0; ks < 4; ++ks) {            // 4 k16-steps (BKE=64)
            const int cur = ks & 1;
            const int nxt = cur ^ 1;
            if (ks < 3) {                            // prefetch frags(ks+1)
                const uint32_t cOff = (uint32_t)(ks + 1) * 32;  // 16 fp16 = 32B
#pragma unroll
                for (int nj = 0; nj < 2; ++nj) {
                    uint32_t q[4];
                    ldmatrix_x4(q, bB + nj * 16 * ROWB + cOff);
                    rb[nxt][2 * nj][0] = q[0]; rb[nxt][2 * nj][1] = q[1];
                    rb[nxt][2 * nj + 1][0] = q[2]; rb[nxt][2 * nj + 1][1] = q[3];
                }
#pragma unroll
                for (int mi = 0; mi < 4; ++mi)
                    ldmatrix_x4(ra[nxt][mi], aB + mi * 16 * ROWB + cOff);
            }
#pragma unroll
            for (int mi = 0; mi < 4; ++mi)
#pragma unroll
                for (int ni = 0; ni < 4; ++ni)
                    mma_f16(acc[mi][ni], ra[cur][mi], rb[cur][ni]);
        }
        __syncthreads();
    }

    // Epilogue: out = scale[o]*acc + bias[o]
#pragma unroll
    for (int mi = 0; mi < 4; ++mi) {
#pragma unroll
        for (int ni = 0; ni < 4; ++ni) {
            int row = bm + wm * 64 + mi * 16 + (lane >> 2);
            int col = bn + wn * 32 + ni * 8 + (lane & 3) * 2;
            float s0 = __ldg(scales + col), s1 = __ldg(scales + col + 1);
            float b0 = __ldg(bias + col),   b1 = __ldg(bias + col + 1);
            float2 v0 = make_float2(fmaf(acc[mi][ni][0], s0, b0),
                                    fmaf(acc[mi][ni][1], s1, b1));
            float2 v1 = make_float2(fmaf(acc[mi][ni][2], s0, b0),
                                    fmaf(acc[mi][ni][3], s1, b1));
            *reinterpret_cast<float2*>(out + (size_t)row * OUTF + col) = v0;
            *reinterpret_cast<float2*>(out + (size_t)(row + 8) * OUTF + col) = v1;
        }
    }
}

// ---------------------------------------------------------------------------
// Launch
// ---------------------------------------------------------------------------
extern "C" void kernel_launch(void* const* d_in, const int* in_sizes, int n_in,
                              void* d_out, int out_size) {
    const float* x      = (const float*)d_in[0];
    const int*   wp     = (const int*)d_in[1];
    const float* scales = (const float*)d_in[2];
    const float* bias   = (const float*)d_in[3];
    float*       out    = (float*)d_out;
    (void)in_sizes; (void)n_in; (void)out_size;

    prep_kernel<<<XB + WB, 256>>>(x, wp);

    cudaFuncSetAttribute(gemm_f16, cudaFuncAttributeMaxDynamicSharedMemorySize, SMEM_TOTAL);
    dim3 grid(OUTF / BN, NROWS / BM);   // (16, 32)
    gemm_f16<<<grid, NTHREADS, SMEM_TOTAL>>>(out, scales, bias);
}

// round 17
// speedup vs baseline: 1.1405x; 1.1405x over previous
#include <cuda_runtime.h>
#include <cuda_fp16.h>
#include <cstdint>
#include <cstddef>

// Problem constants
#define NROWS 4096
#define INF   4096
#define OUTF  4096

// GEMM tiling (fp16 HMMA) — R9 geometry
#define BM 128
#define BN 128
#define BKE 64                    // fp16 elements per k-tile
#define STAGES 3
#define KT (INF / BKE)            // 64
#define LDSE 72                   // padded smem row stride in fp16 (144 B)
#define ROWB (LDSE * 2)           // 144 bytes/row
#define TILE_B (128 * ROWB)       // 18432 per tile
#define STAGE_B (2 * TILE_B)      // X + W = 36864
#define SMEM_TOTAL (STAGES * STAGE_B)   // 110592 -> 2 CTAs/SM (221184)

#define NTHREADS 256

// Persistent scratch
__device__ __half g_x[(size_t)NROWS * INF];   // fp16(x)
__device__ __half g_w[(size_t)OUTF  * INF];   // (q - 8) exact

// ---------------------------------------------------------------------------
// Fused prep: blocks [0, XB) convert x; blocks [XB, XB+WB) unpack w
// ---------------------------------------------------------------------------
#define XB ((NROWS * INF / 4) / 256)          // 16384 blocks
#define WB ((OUTF * (INF / 2) / 4) / 256)     // 8192 blocks

__global__ void prep_kernel(const float* __restrict__ x, const int* __restrict__ wp) {
    if (blockIdx.x < XB) {
        int idx = blockIdx.x * blockDim.x + threadIdx.x;
        float4 v = reinterpret_cast<const float4*>(x)[idx];
        __half2 h01 = __floats2half2_rn(v.x, v.y);
        __half2 h23 = __floats2half2_rn(v.z, v.w);
        uint2 pack;
        pack.x = *reinterpret_cast<uint32_t*>(&h01);
        pack.y = *reinterpret_cast<uint32_t*>(&h23);
        reinterpret_cast<uint2*>(g_x)[idx] = pack;
    } else {
        int idx = (blockIdx.x - XB) * blockDim.x + threadIdx.x;
        int4 w = reinterpret_cast<const int4*>(wp)[idx];
        int vals[4] = {w.x, w.y, w.z, w.w};
        __half ob[8];
#pragma unroll
        for (int j = 0; j < 4; ++j) {
            ob[2 * j]     = __int2half_rn((vals[j] & 0xF) - 8);
            ob[2 * j + 1] = __int2half_rn(((vals[j] >> 4) & 0xF) - 8);
        }
        reinterpret_cast<uint4*>(&g_w[(size_t)idx * 8])[0] = *reinterpret_cast<uint4*>(ob);
    }
}

// ---------------------------------------------------------------------------
// GEMM helpers
// ---------------------------------------------------------------------------
#define CP_ASYNC16(dst, src) \
    asm volatile("cp.async.cg.shared.global [%0], [%1], 16;\n" :: "r"(dst), "l"(src))
#define CP_COMMIT() asm volatile("cp.async.commit_group;\n" ::)
#define CP_WAIT(n)  asm volatile("cp.async.wait_group %0;\n" :: "n"(n))

__device__ __forceinline__ void ldmatrix_x4(uint32_t* r, uint32_t addr) {
    asm volatile("ldmatrix.sync.aligned.m8n8.x4.shared.b16 {%0,%1,%2,%3}, [%4];\n"
                 : "=r"(r[0]), "=r"(r[1]), "=r"(r[2]), "=r"(r[3]) : "r"(addr));
}
__device__ __forceinline__ void mma_f16(float* d, const uint32_t* a, const uint32_t* b) {
    asm volatile("mma.sync.aligned.m16n8k16.row.col.f32.f16.f16.f32 "
                 "{%0,%1,%2,%3}, {%4,%5,%6,%7}, {%8,%9}, {%0,%1,%2,%3};\n"
                 : "+f"(d[0]), "+f"(d[1]), "+f"(d[2]), "+f"(d[3])
                 : "r"(a[0]), "r"(a[1]), "r"(a[2]), "r"(a[3]), "r"(b[0]), "r"(b[1]));
}

// Load one stage: X tile (128 x 64 fp16) + W tile (128 x 64 fp16), 256 threads
__device__ __forceinline__ void load_tile(int tid, int bm, int bn, int stage, int kt,
                                          uint32_t sbase) {
    const int kb = kt * BKE;
    uint32_t dst = sbase + stage * STAGE_B;
#pragma unroll
    for (int i = 0; i < 4; ++i) {
        int chunk = tid + i * NTHREADS;      // 0..1023
        int row = chunk >> 3;
        int c   = chunk & 7;
        uint32_t off = row * ROWB + c * 16;
        CP_ASYNC16(dst + off,          &g_x[(size_t)(bm + row) * INF + kb + c * 8]);
        CP_ASYNC16(dst + TILE_B + off, &g_w[(size_t)(bn + row) * INF + kb + c * 8]);
    }
}

// ---------------------------------------------------------------------------
// GEMM: out[n,o] = (x . w) * wscale[o] + bias[o]
// 8 warps: wm = warp&1 (64 M rows), wn = warp>>1 (32 N cols). Warp tile 64x32.
// Single barrier per k-tile; warp-skewed k-step order to decorrelate
// ldmatrix/MMA bursts across warps.
// ---------------------------------------------------------------------------
__global__ void __launch_bounds__(NTHREADS, 2) gemm_f16(
    float* __restrict__ out,
    const float* __restrict__ scales,
    const float* __restrict__ bias)
{
    extern __shared__ char smem[];
    const int tid  = threadIdx.x;
    const int lane = tid & 31;
    const int warp = tid >> 5;
    const int wm   = warp & 1;     // 2 warps along M (64 rows)
    const int wn   = warp >> 1;    // 4 warps along N (32 cols)
    const int bm   = blockIdx.y * BM;
    const int bn   = blockIdx.x * BN;

    uint32_t sb = (uint32_t)__cvta_generic_to_shared(smem);

    // Per-warp ldmatrix base offsets within a stage
    const uint32_t aOff = (uint32_t)(wm * 64 + (lane & 15)) * ROWB
                        + ((lane >> 4) << 3) * 2;
    const uint32_t bOff = TILE_B
                        + (uint32_t)(wn * 32 + ((lane >> 4) << 3) + (lane & 7)) * ROWB
                        + (((lane >> 3) & 1) << 3) * 2;

    float acc[4][4][4];
#pragma unroll
    for (int mi = 0; mi < 4; ++mi)
#pragma unroll
        for (int ni = 0; ni < 4; ++ni)
#pragma unroll
            for (int j = 0; j < 4; ++j) acc[mi][ni][j] = 0.0f;

    // Prologue: stages 0,1
#pragma unroll
    for (int s = 0; s < STAGES - 1; ++s) {
        load_tile(tid, bm, bn, s, s, sb);
        CP_COMMIT();
    }

    int s_cur = 0, s_ld = STAGES - 1;
    for (int kt = 0; kt < KT; ++kt) {
        CP_WAIT(STAGES - 2);
        __syncthreads();                       // single barrier per k-tile

        int ld = kt + STAGES - 1;
        if (ld < KT) load_tile(tid, bm, bn, s_ld, ld, sb);
        CP_COMMIT();

        const uint32_t stBase = sb + s_cur * STAGE_B;
        const uint32_t aB = stBase + aOff;
        const uint32_t bB = stBase + bOff;

#pragma unroll
        for (int s = 0; s < 4; ++s) {
            // warp-skewed k16 step: accumulation order is warp-local permutation
            const uint32_t cOff = (uint32_t)(((s + warp) & 3) * 32);  // 16 fp16 = 32B
            uint32_t rb[4][2];
#pragma unroll
            for (int nj = 0; nj < 2; ++nj) {
                uint32_t q[4];
                ldmatrix_x4(q, bB + nj * 16 * ROWB + cOff);
                rb[2 * nj][0] = q[0]; rb[2 * nj][1] = q[1];
                rb[2 * nj + 1][0] = q[2]; rb[2 * nj + 1][1] = q[3];
            }
            uint32_t ra[4][4];
#pragma unroll
            for (int mi = 0; mi < 4; ++mi)
                ldmatrix_x4(ra[mi], aB + mi * 16 * ROWB + cOff);
#pragma unroll
            for (int mi = 0; mi < 4; ++mi)
#pragma unroll
                for (int ni = 0; ni < 4; ++ni)
                    mma_f16(acc[mi][ni], ra[mi], rb[ni]);
        }
        // NOTE: no bottom barrier — the top barrier of the next iteration
        // orders this iteration's ldmatrix reads before the stage overwrite.
        s_cur = (s_cur + 1 == STAGES) ? 0 : s_cur + 1;
        s_ld  = (s_ld  + 1 == STAGES) ? 0 : s_ld + 1;
    }

    // Epilogue: out = scale[o]*acc + bias[o]
#pragma unroll
    for (int mi = 0; mi < 4; ++mi) {
#pragma unroll
        for (int ni = 0; ni < 4; ++ni) {
            int row = bm + wm * 64 + mi * 16 + (lane >> 2);
            int col = bn + wn * 32 + ni * 8 + (lane & 3) * 2;
            float s0 = __ldg(scales + col), s1 = __ldg(scales + col + 1);
            float b0 = __ldg(bias + col),   b1 = __ldg(bias + col + 1);
            float2 v0 = make_float2(fmaf(acc[mi][ni][0], s0, b0),
                                    fmaf(acc[mi][ni][1], s1, b1));
            float2 v1 = make_float2(fmaf(acc[mi][ni][2], s0, b0),
                                    fmaf(acc[mi][ni][3], s1, b1));
            *reinterpret_cast<float2*>(out + (size_t)row * OUTF + col) = v0;
            *reinterpret_cast<float2*>(out + (size_t)(row + 8) * OUTF + col) = v1;
        }
    }
}

// ---------------------------------------------------------------------------
// Launch
// ---------------------------------------------------------------------------
extern "C" void kernel_launch(void* const* d_in, const int* in_sizes, int n_in,
                              void* d_out, int out_size) {
    const float* x      = (const float*)d_in[0];
    const int*   wp     = (const int*)d_in[1];
    const float* scales = (const float*)d_in[2];
    const float* bias   = (const float*)d_in[3];
    float*       out    = (float*)d_out;
    (void)in_sizes; (void)n_in; (void)out_size;

    prep_kernel<<<XB + WB, 256>>>(x, wp);

    cudaFuncSetAttribute(gemm_f16, cudaFuncAttributeMaxDynamicSharedMemorySize, SMEM_TOTAL);
    dim3 grid(OUTF / BN, NROWS / BM);   // (32, 32)
    gemm_f16<<<grid, NTHREADS, SMEM_TOTAL>>>(out, scales, bias);
}